// round 2
// baseline (speedup 1.0000x reference)
#include <cuda_runtime.h>
#include <math.h>

#define NROWS 8192
#define KCB   8192
#define DD    512
#define NDTOT (NROWS*DD)

#define BM   128
#define BD   32
#define BDP  36
#define BKP  130

// Xd: transposed+duplicated X tile, stride 258 floats (8B-aligned rows, 2-way max store conflicts)
#define XDS  258
// Cs: codebook tile, stride 130 floats (2-way max store conflicts)
#define CSS  130
#define SMEM_NEAREST ((BD*XDS + BD*CSS)*4)

// ---------------- device scratch (no allocation allowed) ----------------
__device__ float g_codebook[KCB*DD];   // 16 MB projected codebook
__device__ float g_cbsq[KCB];
__device__ int   g_idx[2*NROWS];
__device__ int   g_counts[2*KCB];
__device__ float g_part[NROWS*4];

typedef unsigned long long ull;

// packed f32x2 helpers (FFMA2: 2x fp32 FMA throughput on sm_103a)
__device__ __forceinline__ ull bcast2(float x){
    ull r; asm("mov.b64 %0, {%1, %1};" : "=l"(r) : "r"(__float_as_uint(x))); return r;
}
__device__ __forceinline__ void fma2(ull &d, ull a, ull b){
    asm("fma.rn.f32x2 %0, %1, %2, %0;" : "+l"(d) : "l"(a), "l"(b));
}
__device__ __forceinline__ float lo2(ull v){ return __uint_as_float((unsigned)v); }
__device__ __forceinline__ float hi2(ull v){ return __uint_as_float((unsigned)(v >> 32)); }

// ---------------- init ----------------
__global__ void init_kernel(){
    int i = blockIdx.x * blockDim.x + threadIdx.x;
    if (i < 2*KCB) g_counts[i] = 0;
}

// ---------------- codebook projection: C[k,d] = sum_j E[k,j]*W[d,j] + b[d] ----------------
__global__ __launch_bounds__(256, 1) void proj_kernel(
    const float* __restrict__ E, const float* __restrict__ W, const float* __restrict__ bias)
{
    __shared__ __align__(16) float As[BM][BDP];
    __shared__ __align__(16) float Ws[BD][BKP];
    const int tid = threadIdx.x;
    const int tx = tid & 15, ty = tid >> 4;
    const int m0 = blockIdx.x * BM;
    const int n0 = blockIdx.y * 128;
    const int lrow = tid >> 3, lc4 = (tid & 7) * 4;
    const int crow = tid >> 5, ccol = tid & 31;

    ull acc[8][4];
#pragma unroll
    for (int i = 0; i < 8; i++)
#pragma unroll
        for (int j = 0; j < 4; j++) acc[i][j] = 0ULL;

    float4 apre[4]; float wpre[16];
#pragma unroll
    for (int t = 0; t < 4; t++)
        apre[t] = *reinterpret_cast<const float4*>(&E[(m0 + lrow + 32*t)*DD + lc4]);
#pragma unroll
    for (int p = 0; p < 16; p++)
        wpre[p] = W[(n0 + p*8 + crow)*DD + ccol];

    for (int j0 = 0; j0 < DD; j0 += BD) {
        __syncthreads();
#pragma unroll
        for (int t = 0; t < 4; t++)
            *reinterpret_cast<float4*>(&As[lrow + 32*t][lc4]) = apre[t];
#pragma unroll
        for (int p = 0; p < 16; p++)
            Ws[ccol][p*8 + crow] = wpre[p];
        __syncthreads();
        if (j0 + BD < DD) {
            const int jn = j0 + BD;
#pragma unroll
            for (int t = 0; t < 4; t++)
                apre[t] = *reinterpret_cast<const float4*>(&E[(m0 + lrow + 32*t)*DD + jn + lc4]);
#pragma unroll
            for (int p = 0; p < 16; p++)
                wpre[p] = W[(n0 + p*8 + crow)*DD + jn + ccol];
        }
#pragma unroll 8
        for (int d = 0; d < BD; d++) {
            ull xp[8], cp[4];
#pragma unroll
            for (int j = 0; j < 4; j++)
                cp[j] = *reinterpret_cast<const ull*>(&Ws[d][32*j + 2*tx]);
#pragma unroll
            for (int i = 0; i < 8; i++)
                xp[i] = bcast2(As[ty*8 + i][d]);
#pragma unroll
            for (int i = 0; i < 8; i++)
#pragma unroll
                for (int j = 0; j < 4; j++)
                    fma2(acc[i][j], xp[i], cp[j]);
        }
    }
#pragma unroll
    for (int j = 0; j < 4; j++) {
        const int col = n0 + 32*j + 2*tx;
        const float2 bb = *reinterpret_cast<const float2*>(&bias[col]);
#pragma unroll
        for (int i = 0; i < 8; i++) {
            float2 v;
            v.x = lo2(acc[i][j]) + bb.x;
            v.y = hi2(acc[i][j]) + bb.y;
            *reinterpret_cast<float2*>(&g_codebook[(m0 + ty*8 + i)*DD + col]) = v;
        }
    }
}

// ---------------- cb_sq[k] = ||codebook_k||^2 ----------------
__global__ void cbsq_kernel(){
    const int row = blockIdx.x;
    const int t = threadIdx.x;
    float4 v = *reinterpret_cast<const float4*>(&g_codebook[row*DD + t*4]);
    float s = v.x*v.x + v.y*v.y + v.z*v.z + v.w*v.w;
#pragma unroll
    for (int off = 16; off > 0; off >>= 1) s += __shfl_xor_sync(0xFFFFFFFFu, s, off);
    __shared__ float ws[4];
    if ((t & 31) == 0) ws[t >> 5] = s;
    __syncthreads();
    if (t == 0) g_cbsq[row] = ws[0] + ws[1] + ws[2] + ws[3];
}

// ---------------- fused nearest-codebook search (argmin over K of cb_sq - 2 x.c) ----------------
// Xd layout: Xd[d][2r] = Xd[d][2r+1] = X[m0+r][d0+d]  -> LDS.64 yields ready (x,x) FFMA2 operand.
__global__ __launch_bounds__(256, 1) void nearest_kernel(
    const float* __restrict__ Xsc, const float* __restrict__ Xr)
{
    extern __shared__ float smem[];
    float (*Xd)[XDS] = reinterpret_cast<float (*)[XDS]>(smem);
    float (*Cs)[CSS] = reinterpret_cast<float (*)[CSS]>(smem + BD*XDS);

    const int tid = threadIdx.x;
    const int tx = tid & 15, ty = tid >> 4;
    const int mblk = blockIdx.x;                     // 0..127 : stacked [sc; ribo]
    const float* __restrict__ X = (mblk < 64) ? Xsc : Xr;
    const int m0 = (mblk & 63) * BM;
    const int lrow = tid >> 3, lc4 = (tid & 7) * 4;
    const int crow = tid >> 5, ccol = tid & 31;

    float minv[8]; int mini[8];
#pragma unroll
    for (int i = 0; i < 8; i++){ minv[i] = 3.4e38f; mini[i] = 0; }

    for (int k0 = 0; k0 < KCB; k0 += 128) {
        ull acc[8][4];
#pragma unroll
        for (int i = 0; i < 8; i++)
#pragma unroll
            for (int j = 0; j < 4; j++) acc[i][j] = 0ULL;

        float4 xpre[4]; float cpre[16];
#pragma unroll
        for (int t = 0; t < 4; t++)
            xpre[t] = *reinterpret_cast<const float4*>(&X[(m0 + lrow + 32*t)*DD + lc4]);
#pragma unroll
        for (int p = 0; p < 16; p++)
            cpre[p] = g_codebook[(k0 + p*8 + crow)*DD + ccol];

        for (int d0 = 0; d0 < DD; d0 += BD) {
            __syncthreads();
            // store X transposed + duplicated
#pragma unroll
            for (int t = 0; t < 4; t++) {
                const int r2 = 2*(lrow + 32*t);
                float4 v = xpre[t];
                *reinterpret_cast<float2*>(&Xd[lc4+0][r2]) = make_float2(v.x, v.x);
                *reinterpret_cast<float2*>(&Xd[lc4+1][r2]) = make_float2(v.y, v.y);
                *reinterpret_cast<float2*>(&Xd[lc4+2][r2]) = make_float2(v.z, v.z);
                *reinterpret_cast<float2*>(&Xd[lc4+3][r2]) = make_float2(v.w, v.w);
            }
#pragma unroll
            for (int p = 0; p < 16; p++)
                Cs[ccol][p*8 + crow] = cpre[p];
            __syncthreads();
            if (d0 + BD < DD) {
                const int dn = d0 + BD;
#pragma unroll
                for (int t = 0; t < 4; t++)
                    xpre[t] = *reinterpret_cast<const float4*>(&X[(m0 + lrow + 32*t)*DD + dn + lc4]);
#pragma unroll
                for (int p = 0; p < 16; p++)
                    cpre[p] = g_codebook[(k0 + p*8 + crow)*DD + dn + ccol];
            }
#pragma unroll 8
            for (int d = 0; d < BD; d++) {
                ull xp[8], cp[4];
#pragma unroll
                for (int i = 0; i < 8; i++)
                    xp[i] = *reinterpret_cast<const ull*>(&Xd[d][16*ty + 2*i]);
                cp[0] = *reinterpret_cast<const ull*>(&Cs[d][4*tx]);
                cp[1] = *reinterpret_cast<const ull*>(&Cs[d][4*tx + 2]);
                cp[2] = *reinterpret_cast<const ull*>(&Cs[d][64 + 4*tx]);
                cp[3] = *reinterpret_cast<const ull*>(&Cs[d][64 + 4*tx + 2]);
#pragma unroll
                for (int i = 0; i < 8; i++)
#pragma unroll
                    for (int j = 0; j < 4; j++)
                        fma2(acc[i][j], xp[i], cp[j]);
            }
        }
        // argmin update for this codebook tile
        // acc[i][j]: j=0 -> k0+4tx+{0,1}; j=1 -> +{2,3}; j=2 -> k0+64+4tx+{0,1}; j=3 -> +{2,3}
#pragma unroll
        for (int j = 0; j < 4; j++) {
            const int kk = k0 + ((j >> 1) << 6) + 4*tx + ((j & 1) << 1);
            const float2 cq = *reinterpret_cast<const float2*>(&g_cbsq[kk]);
#pragma unroll
            for (int i = 0; i < 8; i++) {
                float s0 = cq.x - 2.0f * lo2(acc[i][j]);
                float s1 = cq.y - 2.0f * hi2(acc[i][j]);
                if (s0 < minv[i]) { minv[i] = s0; mini[i] = kk; }
                if (s1 < minv[i]) { minv[i] = s1; mini[i] = kk + 1; }
            }
        }
    }
    // reduce across the 16 tx lanes (same 8 rows), tie-break to lowest index
#pragma unroll
    for (int i = 0; i < 8; i++) {
        float v = minv[i]; int id = mini[i];
#pragma unroll
        for (int off = 1; off < 16; off <<= 1) {
            float ov = __shfl_xor_sync(0xFFFFFFFFu, v, off);
            int   oi = __shfl_xor_sync(0xFFFFFFFFu, id, off);
            if (ov < v || (ov == v && oi < id)) { v = ov; id = oi; }
        }
        if (tx == 0) g_idx[mblk*BM + ty*8 + i] = id;
    }
}

// ---------------- histogram ----------------
__global__ void hist_kernel(){
    int i = blockIdx.x * blockDim.x + threadIdx.x;
    if (i < NROWS)            atomicAdd(&g_counts[g_idx[i]], 1);
    else if (i < 2*NROWS)     atomicAdd(&g_counts[KCB + g_idx[i]], 1);
}

// ---------------- gather + straight-through outputs + loss partial sums ----------------
__global__ void gather_kernel(const float* __restrict__ Xsc, const float* __restrict__ Xr,
                              float* __restrict__ out)
{
    const int n = blockIdx.x, t = threadIdx.x;
    const int isc = g_idx[n];
    const int ir  = g_idx[NROWS + n];
    const int off = n*DD + t*4;
    float4 xs = *reinterpret_cast<const float4*>(&Xsc[off]);
    float4 xr = *reinterpret_cast<const float4*>(&Xr[off]);
    float4 qs = *reinterpret_cast<const float4*>(&g_codebook[isc*DD + t*4]);
    float4 qr = *reinterpret_cast<const float4*>(&g_codebook[ir*DD + t*4]);

    float4 os, orr;
    os.x = xs.x + (qs.x - xs.x); os.y = xs.y + (qs.y - xs.y);
    os.z = xs.z + (qs.z - xs.z); os.w = xs.w + (qs.w - xs.w);
    orr.x = xr.x + (qr.x - xr.x); orr.y = xr.y + (qr.y - xr.y);
    orr.z = xr.z + (qr.z - xr.z); orr.w = xr.w + (qr.w - xr.w);
    *reinterpret_cast<float4*>(&out[off])         = os;
    *reinterpret_cast<float4*>(&out[NDTOT + off]) = orr;

    float s1 = 0, s2 = 0, s3 = 0, s4 = 0;
    {
        float d;
        d = xs.x - qs.x; s1 += d*d;  d = xs.y - qs.y; s1 += d*d;
        d = xs.z - qs.z; s1 += d*d;  d = xs.w - qs.w; s1 += d*d;
        d = xr.x - qr.x; s2 += d*d;  d = xr.y - qr.y; s2 += d*d;
        d = xr.z - qr.z; s2 += d*d;  d = xr.w - qr.w; s2 += d*d;
        d = qr.x - xs.x; s3 += d*d;  d = qr.y - xs.y; s3 += d*d;
        d = qr.z - xs.z; s3 += d*d;  d = qr.w - xs.w; s3 += d*d;
        d = qs.x - xr.x; s4 += d*d;  d = qs.y - xr.y; s4 += d*d;
        d = qs.z - xr.z; s4 += d*d;  d = qs.w - xr.w; s4 += d*d;
    }
#pragma unroll
    for (int o = 16; o > 0; o >>= 1) {
        s1 += __shfl_xor_sync(0xFFFFFFFFu, s1, o);
        s2 += __shfl_xor_sync(0xFFFFFFFFu, s2, o);
        s3 += __shfl_xor_sync(0xFFFFFFFFu, s3, o);
        s4 += __shfl_xor_sync(0xFFFFFFFFu, s4, o);
    }
    __shared__ float4 wred[4];
    if ((t & 31) == 0) wred[t >> 5] = make_float4(s1, s2, s3, s4);
    __syncthreads();
    if (t == 0) {
        float4 a = wred[0];
        a.x += wred[1].x + wred[2].x + wred[3].x;
        a.y += wred[1].y + wred[2].y + wred[3].y;
        a.z += wred[1].z + wred[2].z + wred[3].z;
        a.w += wred[1].w + wred[2].w + wred[3].w;
        *reinterpret_cast<float4*>(&g_part[n*4]) = a;
    }
}

// ---------------- finalize: losses + perplexities ----------------
__global__ void finalize_kernel(float* __restrict__ out)
{
    const int t = threadIdx.x;
    float s1 = 0, s2 = 0, s3 = 0, s4 = 0, e1 = 0, e2 = 0;
    for (int n = t; n < NROWS; n += 256) {
        float4 p = *reinterpret_cast<const float4*>(&g_part[n*4]);
        s1 += p.x; s2 += p.y; s3 += p.z; s4 += p.w;
    }
    const float invN = 1.0f / (float)NROWS;
    for (int k = t; k < KCB; k += 256) {
        int c = g_counts[k];
        if (c > 0) { float p = c * invN; e1 -= p * logf(p + 1e-10f); }
        int c2 = g_counts[KCB + k];
        if (c2 > 0) { float p = c2 * invN; e2 -= p * logf(p + 1e-10f); }
    }
#pragma unroll
    for (int o = 16; o > 0; o >>= 1) {
        s1 += __shfl_xor_sync(0xFFFFFFFFu, s1, o);
        s2 += __shfl_xor_sync(0xFFFFFFFFu, s2, o);
        s3 += __shfl_xor_sync(0xFFFFFFFFu, s3, o);
        s4 += __shfl_xor_sync(0xFFFFFFFFu, s4, o);
        e1 += __shfl_xor_sync(0xFFFFFFFFu, e1, o);
        e2 += __shfl_xor_sync(0xFFFFFFFFu, e2, o);
    }
    __shared__ float red[8][6];
    if ((t & 31) == 0) {
        int w = t >> 5;
        red[w][0] = s1; red[w][1] = s2; red[w][2] = s3;
        red[w][3] = s4; red[w][4] = e1; red[w][5] = e2;
    }
    __syncthreads();
    if (t == 0) {
        float S1 = 0, S2 = 0, S3 = 0, S4 = 0, E1 = 0, E2 = 0;
        for (int w = 0; w < 8; w++) {
            S1 += red[w][0]; S2 += red[w][1]; S3 += red[w][2];
            S4 += red[w][3]; E1 += red[w][4]; E2 += red[w][5];
        }
        const float invND = 1.0f / (float)NDTOT;
        out[2*NDTOT + 0] = 0.5f * S1 * invND;
        out[2*NDTOT + 1] = (0.25f*S1 + 0.75f*S2 + 0.125f*S3 + 0.125f*S4) * invND;
        out[2*NDTOT + 2] = expf(E1);
        out[2*NDTOT + 3] = expf(E2);
    }
}

// ---------------- launch ----------------
extern "C" void kernel_launch(void* const* d_in, const int* in_sizes, int n_in,
                              void* d_out, int out_size)
{
    const float* xsc = (const float*)d_in[0];   // scRNA_semantic [8192,512]
    const float* xr  = (const float*)d_in[1];   // ribo_semantic  [8192,512]
    const float* emb = (const float*)d_in[2];   // emb_weight     [8192,512]
    const float* pw  = (const float*)d_in[3];   // proj_w         [512,512]
    const float* pb  = (const float*)d_in[4];   // proj_b         [512]
    float* out = (float*)d_out;                 // [2*N*D + 4]

    // >48KB dynamic smem for nearest_kernel (not an allocation; capture-safe)
    cudaFuncSetAttribute(nearest_kernel,
                         cudaFuncAttributeMaxDynamicSharedMemorySize, SMEM_NEAREST);

    init_kernel<<<64, 256>>>();
    proj_kernel<<<dim3(KCB/BM, DD/128), 256>>>(emb, pw, pb);
    cbsq_kernel<<<KCB, 128>>>();
    nearest_kernel<<<128, 256, SMEM_NEAREST>>>(xsc, xr);
    hist_kernel<<<64, 256>>>();
    gather_kernel<<<NROWS, 128>>>(xsc, xr, out);
    finalize_kernel<<<1, 256>>>(out);
}

// round 7
// speedup vs baseline: 1.2577x; 1.2577x over previous
#include <cuda_runtime.h>
#include <math.h>

#define NROWS 8192
#define KCB   8192
#define DD    512
#define NDTOT (NROWS*DD)

#define BM   128
#define BD   32

// proj kernel tiles
#define BDP  36
#define BKP  130

// nearest kernel: split-K + double-buffered smem
#define SPLITS 8
#define KSLICE (KCB/SPLITS)                 // 1024
#define TILES_PER_SPLIT (KSLICE/128)        // 8
#define NCHUNK (TILES_PER_SPLIT*16)         // 128 chunks of 32 d
#define XSS 132                              // Xs row stride (words)
#define CDS 260                              // Cd row stride (words), duplicated k
#define STAGE_W (BD*XSS + BD*CDS)            // 12544 words per stage
#define SMEM_NEAREST (2*STAGE_W*4)           // 100352 B

// ---------------- device scratch (no allocation allowed) ----------------
__device__ float g_codebook[KCB*DD];   // 16 MB projected codebook
__device__ float g_cbsq[KCB];
__device__ int   g_idx[2*NROWS];
__device__ int   g_counts[2*KCB];
__device__ float g_part[NROWS*4];
__device__ float g_pminv[SPLITS*2*NROWS];
__device__ int   g_pmini[SPLITS*2*NROWS];

typedef unsigned long long ull;

// packed f32x2 helpers (FFMA2: 2x fp32 FMA throughput on sm_103a)
__device__ __forceinline__ ull bcast2(float x){
    ull r; asm("mov.b64 %0, {%1, %1};" : "=l"(r) : "r"(__float_as_uint(x))); return r;
}
__device__ __forceinline__ void fma2(ull &d, ull a, ull b){
    asm("fma.rn.f32x2 %0, %1, %2, %0;" : "+l"(d) : "l"(a), "l"(b));
}
__device__ __forceinline__ float lo2(ull v){ return __uint_as_float((unsigned)v); }
__device__ __forceinline__ float hi2(ull v){ return __uint_as_float((unsigned)(v >> 32)); }

// ---------------- init ----------------
__global__ void init_kernel(){
    int i = blockIdx.x * blockDim.x + threadIdx.x;
    if (i < 2*KCB) g_counts[i] = 0;
}

// ---------------- codebook projection: C[k,d] = sum_j E[k,j]*W[d,j] + b[d] ----------------
__global__ __launch_bounds__(256, 1) void proj_kernel(
    const float* __restrict__ E, const float* __restrict__ W, const float* __restrict__ bias)
{
    __shared__ __align__(16) float As[BM][BDP];
    __shared__ __align__(16) float Ws[BD][BKP];
    const int tid = threadIdx.x;
    const int tx = tid & 15, ty = tid >> 4;
    const int m0 = blockIdx.x * BM;
    const int n0 = blockIdx.y * 128;
    const int lrow = tid >> 3, lc4 = (tid & 7) * 4;
    const int crow = tid >> 5, ccol = tid & 31;

    ull acc[8][4];
#pragma unroll
    for (int i = 0; i < 8; i++)
#pragma unroll
        for (int j = 0; j < 4; j++) acc[i][j] = 0ULL;

    float4 apre[4]; float wpre[16];
#pragma unroll
    for (int t = 0; t < 4; t++)
        apre[t] = *reinterpret_cast<const float4*>(&E[(m0 + lrow + 32*t)*DD + lc4]);
#pragma unroll
    for (int p = 0; p < 16; p++)
        wpre[p] = W[(n0 + p*8 + crow)*DD + ccol];

    for (int j0 = 0; j0 < DD; j0 += BD) {
        __syncthreads();
#pragma unroll
        for (int t = 0; t < 4; t++)
            *reinterpret_cast<float4*>(&As[lrow + 32*t][lc4]) = apre[t];
#pragma unroll
        for (int p = 0; p < 16; p++)
            Ws[ccol][p*8 + crow] = wpre[p];
        __syncthreads();
        if (j0 + BD < DD) {
            const int jn = j0 + BD;
#pragma unroll
            for (int t = 0; t < 4; t++)
                apre[t] = *reinterpret_cast<const float4*>(&E[(m0 + lrow + 32*t)*DD + jn + lc4]);
#pragma unroll
            for (int p = 0; p < 16; p++)
                wpre[p] = W[(n0 + p*8 + crow)*DD + jn + ccol];
        }
#pragma unroll 8
        for (int d = 0; d < BD; d++) {
            ull xp[8], cp[4];
#pragma unroll
            for (int j = 0; j < 4; j++)
                cp[j] = *reinterpret_cast<const ull*>(&Ws[d][32*j + 2*tx]);
#pragma unroll
            for (int i = 0; i < 8; i++)
                xp[i] = bcast2(As[ty*8 + i][d]);
#pragma unroll
            for (int i = 0; i < 8; i++)
#pragma unroll
                for (int j = 0; j < 4; j++)
                    fma2(acc[i][j], xp[i], cp[j]);
        }
    }
#pragma unroll
    for (int j = 0; j < 4; j++) {
        const int col = n0 + 32*j + 2*tx;
        const float2 bb = *reinterpret_cast<const float2*>(&bias[col]);
#pragma unroll
        for (int i = 0; i < 8; i++) {
            float2 v;
            v.x = lo2(acc[i][j]) + bb.x;
            v.y = hi2(acc[i][j]) + bb.y;
            *reinterpret_cast<float2*>(&g_codebook[(m0 + ty*8 + i)*DD + col]) = v;
        }
    }
}

// ---------------- cb_sq[k] = ||codebook_k||^2 ----------------
__global__ void cbsq_kernel(){
    const int row = blockIdx.x;
    const int t = threadIdx.x;
    float4 v = *reinterpret_cast<const float4*>(&g_codebook[row*DD + t*4]);
    float s = v.x*v.x + v.y*v.y + v.z*v.z + v.w*v.w;
#pragma unroll
    for (int off = 16; off > 0; off >>= 1) s += __shfl_xor_sync(0xFFFFFFFFu, s, off);
    __shared__ float ws[4];
    if ((t & 31) == 0) ws[t >> 5] = s;
    __syncthreads();
    if (t == 0) g_cbsq[row] = ws[0] + ws[1] + ws[2] + ws[3];
}

// ---------------- fused nearest-codebook search, split-K x8, double-buffered ----------------
// Accumulator halves pair ROWS (even,odd). X tile: transposed, non-duplicated, rotated
// so transpose stores are conflict-free. C tile: duplicated (c,c) pairs, k = tx+16j
// compute mapping, conflict-free LDS.64.
__global__ __launch_bounds__(256, 1) void nearest_kernel(
    const float* __restrict__ Xsc, const float* __restrict__ Xr)
{
    extern __shared__ float sm[];
    const int tid  = threadIdx.x;
    const int tx   = tid & 15, ty = tid >> 4;
    const int bid  = blockIdx.x;            // 0..SPLITS*128-1
    const int spl  = bid >> 7;              // K split
    const int mblk = bid & 127;             // stacked [sc; ribo] m-blocks
    const float* __restrict__ X = (mblk < 64) ? Xsc : Xr;
    const int m0    = (mblk & 63) * BM;
    const int kbase = spl * KSLICE;
    const int lrow  = tid >> 3, lc4 = (tid & 7) * 4;
    const int crow  = tid >> 5, ccol = tid & 31;

    float minv[8]; int mini[8];
#pragma unroll
    for (int i = 0; i < 8; i++){ minv[i] = 3.4e38f; mini[i] = 0; }

    ull acc[4][8];
#pragma unroll
    for (int a = 0; a < 4; a++)
#pragma unroll
        for (int j = 0; j < 8; j++) acc[a][j] = 0ULL;

    // prologue: load chunk 0 into regs
    float4 xpre[4]; float cpre[16];
#pragma unroll
    for (int t = 0; t < 4; t++)
        xpre[t] = *reinterpret_cast<const float4*>(&X[(m0 + lrow + 32*t)*DD + lc4]);
#pragma unroll
    for (int p = 0; p < 16; p++)
        cpre[p] = g_codebook[(kbase + p*8 + crow)*DD + ccol];

    for (int n = 0; n < NCHUNK; n++) {
        float* Xs = sm + (n & 1) * STAGE_W;
        float* Cd = Xs + BD*XSS;

        // ---- store chunk n regs -> smem (rotated layouts) ----
#pragma unroll
        for (int t = 0; t < 4; t++) {
            const int colb = lrow + 32*t;
            const float v[4] = {xpre[t].x, xpre[t].y, xpre[t].z, xpre[t].w};
#pragma unroll
            for (int c = 0; c < 4; c++) {
                const int d = lc4 + c;
                const int m = d >> 2;
                const int off = (m << 2) ^ ((m & 1) << 4);
                Xs[d*XSS + ((colb + off) & 127)] = v[c];
            }
        }
#pragma unroll
        for (int p = 0; p < 16; p++) {
            const int k = p*8 + crow;
            const int w = (2*k + 2*(ccol >> 3)) & 255;
            *reinterpret_cast<float2*>(&Cd[ccol*CDS + w]) = make_float2(cpre[p], cpre[p]);
        }

        // ---- prefetch chunk n+1 into regs (lands during compute) ----
        if (n + 1 < NCHUNK) {
            const int d0 = ((n+1) & 15) * 32;
            const int k0 = kbase + ((n+1) >> 4) * 128;
#pragma unroll
            for (int t = 0; t < 4; t++)
                xpre[t] = *reinterpret_cast<const float4*>(&X[(m0 + lrow + 32*t)*DD + d0 + lc4]);
#pragma unroll
            for (int p = 0; p < 16; p++)
                cpre[p] = g_codebook[(k0 + p*8 + crow)*DD + d0 + ccol];
        }
        __syncthreads();

        // ---- compute 32 d-steps from this stage ----
#pragma unroll
        for (int d = 0; d < BD; d++) {
            const int m = d >> 2;
            const int off = (m << 2) ^ ((m & 1) << 4);      // compile-time
            const int r = 2*(d >> 3);                       // compile-time
            const ulonglong2 xa = *reinterpret_cast<const ulonglong2*>(
                &Xs[d*XSS + ((8*ty + off) & 127)]);
            const ulonglong2 xb = *reinterpret_cast<const ulonglong2*>(
                &Xs[d*XSS + ((8*ty + 4 + off) & 127)]);
            ull xp[4] = {xa.x, xa.y, xb.x, xb.y};
            ull cp[8];
#pragma unroll
            for (int j = 0; j < 8; j++)
                cp[j] = *reinterpret_cast<const ull*>(
                    &Cd[d*CDS + ((2*(tx + 16*j) + r) & 255)]);
#pragma unroll
            for (int a = 0; a < 4; a++)
#pragma unroll
                for (int j = 0; j < 8; j++)
                    fma2(acc[a][j], xp[a], cp[j]);
        }

        // ---- per-tile argmin epilogue ----
        if ((n & 15) == 15) {
            const int k0 = kbase + (n >> 4) * 128;
#pragma unroll
            for (int j = 0; j < 8; j++) {
                const int k = k0 + tx + 16*j;
                const float cq = __ldg(&g_cbsq[k]);
#pragma unroll
                for (int a = 0; a < 4; a++) {
                    const float s0 = cq - 2.0f * lo2(acc[a][j]);  // row 8ty+2a
                    const float s1 = cq - 2.0f * hi2(acc[a][j]);  // row 8ty+2a+1
                    if (s0 < minv[2*a])   { minv[2*a]   = s0; mini[2*a]   = k; }
                    if (s1 < minv[2*a+1]) { minv[2*a+1] = s1; mini[2*a+1] = k; }
                    acc[a][j] = 0ULL;
                }
            }
        }
    }

    // reduce across the 16 tx lanes (same 8 rows), tie-break to lowest index
#pragma unroll
    for (int i = 0; i < 8; i++) {
        float v = minv[i]; int id = mini[i];
#pragma unroll
        for (int off = 1; off < 16; off <<= 1) {
            float ov = __shfl_xor_sync(0xFFFFFFFFu, v, off);
            int   oi = __shfl_xor_sync(0xFFFFFFFFu, id, off);
            if (ov < v || (ov == v && oi < id)) { v = ov; id = oi; }
        }
        if (tx == 0) {
            g_pminv[spl*2*NROWS + mblk*BM + ty*8 + i] = v;
            g_pmini[spl*2*NROWS + mblk*BM + ty*8 + i] = id;
        }
    }
}

// ---------------- merge split-K partials + histogram (fused) ----------------
__global__ void merge_hist_kernel(){
    int i = blockIdx.x * blockDim.x + threadIdx.x;   // 0..2*NROWS-1
    if (i < 2*NROWS) {
        float best = g_pminv[i];
        int   id   = g_pmini[i];
#pragma unroll
        for (int s = 1; s < SPLITS; s++) {
            float v = g_pminv[s*2*NROWS + i];
            int   j = g_pmini[s*2*NROWS + i];
            if (v < best) { best = v; id = j; }   // strict < : ties keep lower split == lower k
        }
        g_idx[i] = id;
        atomicAdd(&g_counts[(i < NROWS ? 0 : KCB) + id], 1);
    }
}

// ---------------- gather + straight-through outputs + loss partial sums ----------------
__global__ void gather_kernel(const float* __restrict__ Xsc, const float* __restrict__ Xr,
                              float* __restrict__ out)
{
    const int n = blockIdx.x, t = threadIdx.x;
    const int isc = g_idx[n];
    const int ir  = g_idx[NROWS + n];
    const int off = n*DD + t*4;
    float4 xs = *reinterpret_cast<const float4*>(&Xsc[off]);
    float4 xr = *reinterpret_cast<const float4*>(&Xr[off]);
    float4 qs = *reinterpret_cast<const float4*>(&g_codebook[isc*DD + t*4]);
    float4 qr = *reinterpret_cast<const float4*>(&g_codebook[ir*DD + t*4]);

    float4 os, orr;
    os.x = xs.x + (qs.x - xs.x); os.y = xs.y + (qs.y - xs.y);
    os.z = xs.z + (qs.z - xs.z); os.w = xs.w + (qs.w - xs.w);
    orr.x = xr.x + (qr.x - xr.x); orr.y = xr.y + (qr.y - xr.y);
    orr.z = xr.z + (qr.z - xr.z); orr.w = xr.w + (qr.w - xr.w);
    *reinterpret_cast<float4*>(&out[off])         = os;
    *reinterpret_cast<float4*>(&out[NDTOT + off]) = orr;

    float s1 = 0, s2 = 0, s3 = 0, s4 = 0;
    {
        float d;
        d = xs.x - qs.x; s1 += d*d;  d = xs.y - qs.y; s1 += d*d;
        d = xs.z - qs.z; s1 += d*d;  d = xs.w - qs.w; s1 += d*d;
        d = xr.x - qr.x; s2 += d*d;  d = xr.y - qr.y; s2 += d*d;
        d = xr.z - qr.z; s2 += d*d;  d = xr.w - qr.w; s2 += d*d;
        d = qr.x - xs.x; s3 += d*d;  d = qr.y - xs.y; s3 += d*d;
        d = qr.z - xs.z; s3 += d*d;  d = qr.w - xs.w; s3 += d*d;
        d = qs.x - xr.x; s4 += d*d;  d = qs.y - xr.y; s4 += d*d;
        d = qs.z - xr.z; s4 += d*d;  d = qs.w - xr.w; s4 += d*d;
    }
#pragma unroll
    for (int o = 16; o > 0; o >>= 1) {
        s1 += __shfl_xor_sync(0xFFFFFFFFu, s1, o);
        s2 += __shfl_xor_sync(0xFFFFFFFFu, s2, o);
        s3 += __shfl_xor_sync(0xFFFFFFFFu, s3, o);
        s4 += __shfl_xor_sync(0xFFFFFFFFu, s4, o);
    }
    __shared__ float4 wred[4];
    if ((t & 31) == 0) wred[t >> 5] = make_float4(s1, s2, s3, s4);
    __syncthreads();
    if (t == 0) {
        float4 a = wred[0];
        a.x += wred[1].x + wred[2].x + wred[3].x;
        a.y += wred[1].y + wred[2].y + wred[3].y;
        a.z += wred[1].z + wred[2].z + wred[3].z;
        a.w += wred[1].w + wred[2].w + wred[3].w;
        *reinterpret_cast<float4*>(&g_part[n*4]) = a;
    }
}

// ---------------- finalize: losses + perplexities ----------------
__global__ void finalize_kernel(float* __restrict__ out)
{
    const int t = threadIdx.x;
    float s1 = 0, s2 = 0, s3 = 0, s4 = 0, e1 = 0, e2 = 0;
    for (int n = t; n < NROWS; n += 256) {
        float4 p = *reinterpret_cast<const float4*>(&g_part[n*4]);
        s1 += p.x; s2 += p.y; s3 += p.z; s4 += p.w;
    }
    const float invN = 1.0f / (float)NROWS;
    for (int k = t; k < KCB; k += 256) {
        int c = g_counts[k];
        if (c > 0) { float p = c * invN; e1 -= p * logf(p + 1e-10f); }
        int c2 = g_counts[KCB + k];
        if (c2 > 0) { float p = c2 * invN; e2 -= p * logf(p + 1e-10f); }
    }
#pragma unroll
    for (int o = 16; o > 0; o >>= 1) {
        s1 += __shfl_xor_sync(0xFFFFFFFFu, s1, o);
        s2 += __shfl_xor_sync(0xFFFFFFFFu, s2, o);
        s3 += __shfl_xor_sync(0xFFFFFFFFu, s3, o);
        s4 += __shfl_xor_sync(0xFFFFFFFFu, s4, o);
        e1 += __shfl_xor_sync(0xFFFFFFFFu, e1, o);
        e2 += __shfl_xor_sync(0xFFFFFFFFu, e2, o);
    }
    __shared__ float red[8][6];
    if ((t & 31) == 0) {
        int w = t >> 5;
        red[w][0] = s1; red[w][1] = s2; red[w][2] = s3;
        red[w][3] = s4; red[w][4] = e1; red[w][5] = e2;
    }
    __syncthreads();
    if (t == 0) {
        float S1 = 0, S2 = 0, S3 = 0, S4 = 0, E1 = 0, E2 = 0;
        for (int w = 0; w < 8; w++) {
            S1 += red[w][0]; S2 += red[w][1]; S3 += red[w][2];
            S4 += red[w][3]; E1 += red[w][4]; E2 += red[w][5];
        }
        const float invND = 1.0f / (float)NDTOT;
        out[2*NDTOT + 0] = 0.5f * S1 * invND;
        out[2*NDTOT + 1] = (0.25f*S1 + 0.75f*S2 + 0.125f*S3 + 0.125f*S4) * invND;
        out[2*NDTOT + 2] = expf(E1);
        out[2*NDTOT + 3] = expf(E2);
    }
}

// ---------------- launch ----------------
extern "C" void kernel_launch(void* const* d_in, const int* in_sizes, int n_in,
                              void* d_out, int out_size)
{
    const float* xsc = (const float*)d_in[0];   // scRNA_semantic [8192,512]
    const float* xr  = (const float*)d_in[1];   // ribo_semantic  [8192,512]
    const float* emb = (const float*)d_in[2];   // emb_weight     [8192,512]
    const float* pw  = (const float*)d_in[3];   // proj_w         [512,512]
    const float* pb  = (const float*)d_in[4];   // proj_b         [512]
    float* out = (float*)d_out;                 // [2*N*D + 4]

    // >48KB dynamic smem for nearest_kernel (attribute set; not an allocation)
    cudaFuncSetAttribute(nearest_kernel,
                         cudaFuncAttributeMaxDynamicSharedMemorySize, SMEM_NEAREST);

    init_kernel<<<64, 256>>>();
    proj_kernel<<<dim3(KCB/BM, DD/128), 256>>>(emb, pw, pb);
    cbsq_kernel<<<KCB, 128>>>();
    nearest_kernel<<<SPLITS*128, 256, SMEM_NEAREST>>>(xsc, xr);
    merge_hist_kernel<<<64, 256>>>();
    gather_kernel<<<NROWS, 128>>>(xsc, xr, out);
    finalize_kernel<<<1, 256>>>(out);
}